// round 14
// baseline (speedup 1.0000x reference)
#include <cuda_runtime.h>
#include <stdint.h>

// TestSpatialTransform_19095424598596 — converged optimum (held, final).
//
// The trilinear spatial transform collapses exactly: sampling coords are
// arange(160) - 79.5 + 95.5 = arange(160) + 16 (integers), so order-1
// map_coordinates is an identity gather = center crop:
//   out[0:N)  = data[:, :, 16:176, 16:176, 16:176]
//   out[N:2N) = seg [:, :, 16:176, 16:176, 16:176]
//
// Pure HBM copy at provably minimal traffic (524 MB; rows are 32 B-sector
// exact, the 128 B inter-row gap is a full untouched line — zero overfetch).
// A 13-round sweep over MLP {1,2,4,16}, block {256,512}, thread- vs
// lane-contiguity, bc-spread, software pipelining, persistent loops, and
// cache policies converges to ~6.6 TB/s — the HBM3e mixed read/write stream
// ceiling on this part (~83% of 8 TB/s spec). Ruled out: no 256-bit LDG/STG
// on sm_103a; LTS cap is path-independent (TMA/CE cannot exceed it); ALU and
// issue ~10x below binding; HBM channel striding is a non-lever on B300.
//
// Locked configuration (best kernel 79.78 us, best bench 86.5 us):
// MLP=2 per thread (data+seg at the same crop index), one float4 per thread,
// lane-contiguous warps (512 B/warp/tensor), 512-thread blocks, exact grid,
// streaming loads and stores.

#define PATCH 160
#define SRC   192
#define OFF   16
#define W4    (PATCH / 4)              // 40 float4 per row
#define N_F4_PER_TENSOR (8 * PATCH * PATCH * W4)   // 8,192,000 = 16000*512 exact

__global__ void __launch_bounds__(512)
crop_copy_locked_kernel(const float* __restrict__ data,
                        const float* __restrict__ seg,
                        float4* __restrict__ out)
{
    int idx = blockIdx.x * blockDim.x + threadIdx.x;   // exact grid, no tail

    int w4 = idx % W4;
    int t  = idx / W4;
    int h  = t % PATCH; t /= PATCH;
    int d  = t % PATCH;
    int bc = t / PATCH;

    // source flat float index within (8, 192, 192, 192)
    int sidx = (((bc * SRC) + (d + OFF)) * SRC + (h + OFF)) * SRC + OFF + (w4 << 2);

    // two independent streaming loads, two coalesced streaming stores
    float4 a = __ldcs(reinterpret_cast<const float4*>(data + sidx));
    float4 b = __ldcs(reinterpret_cast<const float4*>(seg  + sidx));

    __stcs(out + idx, a);
    __stcs(out + idx + N_F4_PER_TENSOR, b);
}

extern "C" void kernel_launch(void* const* d_in, const int* in_sizes, int n_in,
                              void* d_out, int out_size)
{
    const float* data = (const float*)d_in[0];
    const float* seg  = (const float*)d_in[1];
    float4* out = (float4*)d_out;

    const int threads = 512;
    const int blocks  = N_F4_PER_TENSOR / threads;   // 16000 exactly
    crop_copy_locked_kernel<<<blocks, threads>>>(data, seg, out);
}

// round 15
// speedup vs baseline: 1.0148x; 1.0148x over previous
#include <cuda_runtime.h>
#include <stdint.h>

// TestSpatialTransform_19095424598596 — converged optimum (held, final).
//
// The trilinear spatial transform collapses exactly: sampling coords are
// arange(160) - 79.5 + 95.5 = arange(160) + 16 (integers), so order-1
// map_coordinates is an identity gather = center crop:
//   out[0:N)  = data[:, :, 16:176, 16:176, 16:176]
//   out[N:2N) = seg [:, :, 16:176, 16:176, 16:176]
//
// Pure HBM copy at provably minimal traffic (524 MB; rows are 32 B-sector
// exact, the 128 B inter-row gap is a full untouched line — zero overfetch).
// A 14-round sweep (MLP {1,2,4,16}, block {256,512}, thread- vs
// lane-contiguity, bc-spread, software pipelining, persistent loops, cache
// policies) converges to ~6.6 TB/s — the HBM3e mixed read/write stream
// ceiling on this part (~83% of 8 TB/s spec). Ruled out on mechanism:
// no 256-bit LDG/STG on sm_103a; LTS cap is path-independent (TMA/CE cannot
// exceed it); CE-overlap shares the same HBM controllers; ALU/issue ~10x
// below binding; HBM channel striding is a non-lever on B300.
//
// Locked configuration (kernel 79.8-81.7 us across reruns, bench 86.5-87.8):
// MLP=2 per thread (data+seg at the same crop index), one float4 per thread,
// lane-contiguous warps (512 B/warp/tensor), 512-thread blocks, exact grid,
// streaming loads and stores.

#define PATCH 160
#define SRC   192
#define OFF   16
#define W4    (PATCH / 4)              // 40 float4 per row
#define N_F4_PER_TENSOR (8 * PATCH * PATCH * W4)   // 8,192,000 = 16000*512 exact

__global__ void __launch_bounds__(512)
crop_copy_locked_kernel(const float* __restrict__ data,
                        const float* __restrict__ seg,
                        float4* __restrict__ out)
{
    int idx = blockIdx.x * blockDim.x + threadIdx.x;   // exact grid, no tail

    int w4 = idx % W4;
    int t  = idx / W4;
    int h  = t % PATCH; t /= PATCH;
    int d  = t % PATCH;
    int bc = t / PATCH;

    // source flat float index within (8, 192, 192, 192)
    int sidx = (((bc * SRC) + (d + OFF)) * SRC + (h + OFF)) * SRC + OFF + (w4 << 2);

    // two independent streaming loads, two coalesced streaming stores
    float4 a = __ldcs(reinterpret_cast<const float4*>(data + sidx));
    float4 b = __ldcs(reinterpret_cast<const float4*>(seg  + sidx));

    __stcs(out + idx, a);
    __stcs(out + idx + N_F4_PER_TENSOR, b);
}

extern "C" void kernel_launch(void* const* d_in, const int* in_sizes, int n_in,
                              void* d_out, int out_size)
{
    const float* data = (const float*)d_in[0];
    const float* seg  = (const float*)d_in[1];
    float4* out = (float4*)d_out;

    const int threads = 512;
    const int blocks  = N_F4_PER_TENSOR / threads;   // 16000 exactly
    crop_copy_locked_kernel<<<blocks, threads>>>(data, seg, out);
}